// round 11
// baseline (speedup 1.0000x reference)
#include <cuda_runtime.h>
#include <cuda_bf16.h>
#include <cstdint>

#define NMAX 100000
#define EMAX 600000
#define GMAX 4096
#define H 128
#define FIN 74

// ---------------- scratch (device globals; no allocations allowed) ----------------
__device__ __align__(16) float d_h [(size_t)NMAX * H];   // emb output
__device__ __align__(16) float d_hw[(size_t)NMAX * H];   // h @ W
__device__ __align__(16) float d_hn[(size_t)NMAX * H];   // aggregated messages (pre-BN)
__device__ __align__(16) float d_dinv[NMAX];             // deg -> rsqrt(deg)
__device__ __align__(16) float d_bnstats[2 * H];         // sum, sumsq
__device__ __align__(16) float d_scale[2 * H];           // scale, shift
__device__ __align__(16) float d_gsum[(size_t)GMAX * H];
__device__ __align__(16) int   d_gmax[(size_t)GMAX * H];
__device__ __align__(16) float d_gcnt[GMAX];
// CSR (dst-sorted edges)
__device__ int d_cnt[NMAX];         // edge count per dst (no self-loops)
__device__ int d_start[NMAX];       // CSR row start
__device__ int d_fill[NMAX];        // placement cursor
__device__ int d_esrc[EMAX];        // src node per CSR slot
__device__ int d_bsum[256];         // scan block sums
__device__ int d_boff[256];         // scan block offsets (exclusive)
// pre-split weights: [mat][n][k], mat 0=emb (k>=74 zero), 1..3 = conv layers
__device__ __align__(16) __nv_bfloat16 d_WH[4 * H * H];
__device__ __align__(16) __nv_bfloat16 d_WL[4 * H * H];

// ---------------- degree + histogram ----------------
__global__ void deg_init_kernel(int N) {
    int i = blockIdx.x * blockDim.x + threadIdx.x;
    if (i < N) { d_dinv[i] = 1.0f; d_cnt[i] = 0; }  // self-loop
}
__global__ void deg_edge_kernel(const int* __restrict__ ei, int E) {
    int i = blockIdx.x * blockDim.x + threadIdx.x;
    if (i < E) {
        int d = ei[E + i];
        atomicAdd(&d_dinv[d], 1.0f);
        atomicAdd(&d_cnt[d], 1);
    }
}
__global__ void deg_fin_kernel(int N) {
    int i = blockIdx.x * blockDim.x + threadIdx.x;
    if (i < N) d_dinv[i] = rsqrtf(d_dinv[i]);
}
__global__ void zero_stats_kernel() {
    if (threadIdx.x < 2 * H) d_bnstats[threadIdx.x] = 0.0f;
}

// ---------------- 2-level exclusive scan of d_cnt -> d_start ----------------
__global__ void scan1_kernel(int N) {
    __shared__ int sh[512];
    int t = threadIdx.x;
    int i = blockIdx.x * 512 + t;
    int v = (i < N) ? d_cnt[i] : 0;
    sh[t] = v;
    __syncthreads();
    for (int off = 1; off < 512; off <<= 1) {
        int add = (t >= off) ? sh[t - off] : 0;
        __syncthreads();
        sh[t] += add;
        __syncthreads();
    }
    if (i < N) d_start[i] = sh[t] - v;
    if (t == 511) d_bsum[blockIdx.x] = sh[511];
}
__global__ void scan2_kernel(int nb) {
    __shared__ int sh[512];
    int t = threadIdx.x;
    int v = (t < nb) ? d_bsum[t] : 0;
    sh[t] = v;
    __syncthreads();
    for (int off = 1; off < 512; off <<= 1) {
        int add = (t >= off) ? sh[t - off] : 0;
        __syncthreads();
        sh[t] += add;
        __syncthreads();
    }
    if (t < nb) d_boff[t] = sh[t] - v;
}
__global__ void scan3_kernel(int N) {
    int i = blockIdx.x * blockDim.x + threadIdx.x;
    if (i < N) {
        int s = d_start[i] + d_boff[i >> 9];
        d_start[i] = s;
        d_fill[i] = s;
    }
}
__global__ void place_kernel(const int* __restrict__ ei, int E) {
    int i = blockIdx.x * blockDim.x + threadIdx.x;
    if (i < E) {
        int s = ei[i], d = ei[E + i];
        int pos = atomicAdd(&d_fill[d], 1);
        d_esrc[pos] = s;
    }
}

// ---------------- pre-split weights to bf16 hi/lo, transposed [n][k] ----------------
__global__ void presplit_kernel(const float* __restrict__ embW,
                                const float* __restrict__ convW) {
    int i = blockIdx.x * 256 + threadIdx.x;   // < 4*128*128
    int m = i >> 14, n = (i >> 7) & 127, k = i & 127;
    float v = 0.0f;
    if (m == 0) { if (k < FIN) v = embW[k * H + n]; }
    else v = convW[(size_t)(m - 1) * H * H + k * H + n];
    __nv_bfloat16 hv = __float2bfloat16(v);
    d_WH[i] = hv;
    d_WL[i] = __float2bfloat16(v - __bfloat162float(hv));
}

// ---------------- tensor-core GEMM (bf16 split, fp32 accumulate) ----------------
// C[N][128] = A[N][K] @ B[K][128], B pre-split in global (d_WH/d_WL, [n][k]).
// Block: 64 rows, 256 thr (8 warps 2x4, each a 32x32 tile). Only A staged in smem.
// 3 MMAs: ah*bh + al*bh + ah*bl.
// mode 0 (emb): Cout = relu(A@B + bias)
// mode 1 (conv): d_hw = A@B ; d_hn = (A@B)*dinv[row]^2 + bias ; bna: BN+ReLU on A load.
__device__ __forceinline__ void mma_bf16(float* c, const uint32_t* a, const uint32_t* b) {
    asm volatile("mma.sync.aligned.m16n8k16.row.col.f32.bf16.bf16.f32 "
                 "{%0,%1,%2,%3}, {%4,%5,%6,%7}, {%8,%9}, {%0,%1,%2,%3};"
                 : "+f"(c[0]), "+f"(c[1]), "+f"(c[2]), "+f"(c[3])
                 : "r"(a[0]), "r"(a[1]), "r"(a[2]), "r"(a[3]), "r"(b[0]), "r"(b[1]));
}

#define LDK 132   // bf16 per smem row (128 + 4 pad)

__global__ void __launch_bounds__(256)
mma_gemm_kernel(const float* __restrict__ A, int mat,
                const float* __restrict__ bias, float* __restrict__ Cout,
                int N, int K, int mode, int bna) {
    __shared__ __align__(16) __nv_bfloat16 AH[64 * LDK];
    __shared__ __align__(16) __nv_bfloat16 AL[64 * LDK];

    int tid = threadIdx.x;
    int rowBase = blockIdx.x * 64;

    // ---- stage A (64 x 128), split hi/lo ----
    if (K == 128) {
        // vectorized: float4 loads, packed bf16x2 stores
        const float4* A4 = (const float4*)A;
        const float4* sc4 = (const float4*)d_scale;
        for (int i = tid; i < 64 * 32; i += 256) {
            int r = i >> 5, k4 = i & 31;
            int gr = rowBase + r;
            float4 v = make_float4(0.f, 0.f, 0.f, 0.f);
            if (gr < N) v = A4[(size_t)gr * 32 + k4];
            if (bna) {
                float4 s = sc4[k4], b = sc4[32 + k4];
                v.x = fmaxf(fmaf(v.x, s.x, b.x), 0.f);
                v.y = fmaxf(fmaf(v.y, s.y, b.y), 0.f);
                v.z = fmaxf(fmaf(v.z, s.z, b.z), 0.f);
                v.w = fmaxf(fmaf(v.w, s.w, b.w), 0.f);
            }
            __nv_bfloat162 h01 = __floats2bfloat162_rn(v.x, v.y);
            __nv_bfloat162 h23 = __floats2bfloat162_rn(v.z, v.w);
            __nv_bfloat162 l01 = __floats2bfloat162_rn(
                v.x - __bfloat162float(h01.x), v.y - __bfloat162float(h01.y));
            __nv_bfloat162 l23 = __floats2bfloat162_rn(
                v.z - __bfloat162float(h23.x), v.w - __bfloat162float(h23.y));
            uint2 uh, ul;
            uh.x = *reinterpret_cast<uint32_t*>(&h01);
            uh.y = *reinterpret_cast<uint32_t*>(&h23);
            ul.x = *reinterpret_cast<uint32_t*>(&l01);
            ul.y = *reinterpret_cast<uint32_t*>(&l23);
            *(uint2*)&AH[r * LDK + k4 * 4] = uh;
            *(uint2*)&AL[r * LDK + k4 * 4] = ul;
        }
    } else {
        for (int i = tid; i < 64 * 128; i += 256) {
            int r = i >> 7, k = i & 127;
            int gr = rowBase + r;
            float v = 0.0f;
            if (gr < N && k < K) v = A[(size_t)gr * K + k];
            __nv_bfloat16 hv = __float2bfloat16(v);
            AH[r * LDK + k] = hv;
            AL[r * LDK + k] = __float2bfloat16(v - __bfloat162float(hv));
        }
    }
    __syncthreads();

    int lane = tid & 31, wid = tid >> 5;
    int wm = wid & 1;        // m offset 32*wm
    int wn = wid >> 1;       // n offset 32*wn
    int g = lane >> 2, tg = lane & 3;

    const __nv_bfloat16* WHp = d_WH + (size_t)mat * H * H;
    const __nv_bfloat16* WLp = d_WL + (size_t)mat * H * H;

    float acc[2][4][4];
#pragma unroll
    for (int i2 = 0; i2 < 2; i2++)
#pragma unroll
        for (int j = 0; j < 4; j++)
#pragma unroll
            for (int e = 0; e < 4; e++) acc[i2][j][e] = 0.0f;

#pragma unroll 1
    for (int ks = 0; ks < 8; ks++) {
        int k0 = ks * 16;
        uint32_t ah[2][4], alr[2][4], bh[4][2], blr[4][2];
#pragma unroll
        for (int i2 = 0; i2 < 2; i2++) {
            int r = wm * 32 + i2 * 16 + g;
            const uint32_t* ph  = (const uint32_t*)(AH + r * LDK + k0);
            const uint32_t* ph8 = (const uint32_t*)(AH + (r + 8) * LDK + k0);
            const uint32_t* pl  = (const uint32_t*)(AL + r * LDK + k0);
            const uint32_t* pl8 = (const uint32_t*)(AL + (r + 8) * LDK + k0);
            ah[i2][0] = ph[tg];     ah[i2][1] = ph8[tg];
            ah[i2][2] = ph[tg + 4]; ah[i2][3] = ph8[tg + 4];
            alr[i2][0] = pl[tg];     alr[i2][1] = pl8[tg];
            alr[i2][2] = pl[tg + 4]; alr[i2][3] = pl8[tg + 4];
        }
#pragma unroll
        for (int j = 0; j < 4; j++) {
            int n = wn * 32 + j * 8 + g;
            const uint32_t* pb = (const uint32_t*)(WHp + n * H + k0);
            const uint32_t* qb = (const uint32_t*)(WLp + n * H + k0);
            bh[j][0] = pb[tg];  bh[j][1] = pb[tg + 4];
            blr[j][0] = qb[tg]; blr[j][1] = qb[tg + 4];
        }
#pragma unroll
        for (int i2 = 0; i2 < 2; i2++)
#pragma unroll
            for (int j = 0; j < 4; j++) {
                mma_bf16(acc[i2][j], ah[i2], bh[j]);
                mma_bf16(acc[i2][j], alr[i2], bh[j]);
                mma_bf16(acc[i2][j], ah[i2], blr[j]);
            }
    }

    // ---- epilogue ----
#pragma unroll
    for (int i2 = 0; i2 < 2; i2++) {
#pragma unroll
        for (int half = 0; half < 2; half++) {
            int r = rowBase + wm * 32 + i2 * 16 + g + half * 8;
            if (r >= N) continue;
            if (mode == 0) {
#pragma unroll
                for (int j = 0; j < 4; j++) {
                    int c = wn * 32 + j * 8 + tg * 2;
                    float2 o;
                    o.x = fmaxf(acc[i2][j][half * 2 + 0] + bias[c], 0.0f);
                    o.y = fmaxf(acc[i2][j][half * 2 + 1] + bias[c + 1], 0.0f);
                    *(float2*)&Cout[(size_t)r * H + c] = o;
                }
            } else {
                float dv = d_dinv[r];
                float w = dv * dv;
#pragma unroll
                for (int j = 0; j < 4; j++) {
                    int c = wn * 32 + j * 8 + tg * 2;
                    float v0 = acc[i2][j][half * 2 + 0];
                    float v1 = acc[i2][j][half * 2 + 1];
                    *(float2*)&d_hw[(size_t)r * H + c] = make_float2(v0, v1);
                    float2 o;
                    o.x = fmaf(v0, w, bias[c]);
                    o.y = fmaf(v1, w, bias[c + 1]);
                    *(float2*)&d_hn[(size_t)r * H + c] = o;
                }
            }
        }
    }
}

// ---------------- CSR gather + fused BN stats (warp per node, no atomics on hn) ----------------
__global__ void __launch_bounds__(256)
gather_kernel(int N) {
    int tid = threadIdx.x;
    int lane = tid & 31, wid = tid >> 5;
    unsigned n = (unsigned)(blockIdx.x * 8 + wid);
    bool valid = (n < (unsigned)N);

    float4 acc = make_float4(0.f, 0.f, 0.f, 0.f);
    if (valid) {
        float4* hn4 = (float4*)d_hn;
        const float4* hw4 = (const float4*)d_hw;
        acc = hn4[(size_t)n * 32 + lane];
        float4 acc2 = make_float4(0.f, 0.f, 0.f, 0.f);
        int st = d_start[n];
        int en = st + d_cnt[n];
        float dvd = d_dinv[n];
        int e = st;
        for (; e + 1 < en; e += 2) {
            int s0 = d_esrc[e], s1 = d_esrc[e + 1];
            float n0 = d_dinv[s0] * dvd, n1 = d_dinv[s1] * dvd;
            float4 v0 = hw4[(size_t)s0 * 32 + lane];
            float4 v1 = hw4[(size_t)s1 * 32 + lane];
            acc.x = fmaf(v0.x, n0, acc.x);  acc2.x = fmaf(v1.x, n1, acc2.x);
            acc.y = fmaf(v0.y, n0, acc.y);  acc2.y = fmaf(v1.y, n1, acc2.y);
            acc.z = fmaf(v0.z, n0, acc.z);  acc2.z = fmaf(v1.z, n1, acc2.z);
            acc.w = fmaf(v0.w, n0, acc.w);  acc2.w = fmaf(v1.w, n1, acc2.w);
        }
        if (e < en) {
            int s0 = d_esrc[e];
            float n0 = d_dinv[s0] * dvd;
            float4 v0 = hw4[(size_t)s0 * 32 + lane];
            acc.x = fmaf(v0.x, n0, acc.x);
            acc.y = fmaf(v0.y, n0, acc.y);
            acc.z = fmaf(v0.z, n0, acc.z);
            acc.w = fmaf(v0.w, n0, acc.w);
        }
        acc.x += acc2.x; acc.y += acc2.y; acc.z += acc2.z; acc.w += acc2.w;
        hn4[(size_t)n * 32 + lane] = acc;
    }

    // block reduction of BN sum / sumsq (channels 4*lane..4*lane+3)
    __shared__ __align__(16) float4 ssum[8][32];
    __shared__ __align__(16) float4 ssq[8][32];
    float4 sq;
    sq.x = acc.x * acc.x; sq.y = acc.y * acc.y;
    sq.z = acc.z * acc.z; sq.w = acc.w * acc.w;
    ssum[wid][lane] = acc;
    ssq[wid][lane] = sq;
    __syncthreads();
#pragma unroll
    for (int off = 4; off > 0; off >>= 1) {
        if (wid < off) {
            float4 a = ssum[wid][lane], b = ssum[wid + off][lane];
            a.x += b.x; a.y += b.y; a.z += b.z; a.w += b.w;
            ssum[wid][lane] = a;
            float4 c = ssq[wid][lane], d = ssq[wid + off][lane];
            c.x += d.x; c.y += d.y; c.z += d.z; c.w += d.w;
            ssq[wid][lane] = c;
        }
        __syncthreads();
    }
    if (wid == 0) {
        float4 s = ssum[0][lane];
        float4 q = ssq[0][lane];
        asm volatile("red.global.add.v4.f32 [%0], {%1,%2,%3,%4};"
                     :: "l"(&d_bnstats[4 * lane]), "f"(s.x), "f"(s.y), "f"(s.z), "f"(s.w)
                     : "memory");
        asm volatile("red.global.add.v4.f32 [%0], {%1,%2,%3,%4};"
                     :: "l"(&d_bnstats[H + 4 * lane]), "f"(q.x), "f"(q.y), "f"(q.z), "f"(q.w)
                     : "memory");
    }
}

__global__ void bn_finalize_kernel(const float* __restrict__ gamma,
                                   const float* __restrict__ beta, float invN) {
    int c = threadIdx.x;
    float mean = d_bnstats[c] * invN;
    float var = d_bnstats[H + c] * invN - mean * mean;
    float sc = gamma[c] * rsqrtf(var + 1e-5f);
    d_scale[c] = sc;
    d_scale[H + c] = beta[c] - mean * sc;
}

// ---------------- pooling (mean + max per graph), fused BN+ReLU of last layer ----------------
__global__ void pool_init_kernel(int G) {
    int i = blockIdx.x * blockDim.x + threadIdx.x;
    if (i < G * H) { d_gsum[i] = 0.0f; d_gmax[i] = 0; }  // 0 == __float_as_int(0.0f)
    if (i < G) d_gcnt[i] = 0.0f;
}

__global__ void pool_kernel(const int* __restrict__ batch, int N) {
    unsigned i = blockIdx.x * blockDim.x + threadIdx.x;
    unsigned n = i >> 5;
    if (n >= (unsigned)N) return;
    int lane = i & 31;
    int b = batch[n];
    float4 v  = ((const float4*)d_hn)[(size_t)n * 32 + lane];
    float4 sc = ((const float4*)d_scale)[lane];
    float4 sh = ((const float4*)d_scale)[32 + lane];
    v.x = fmaxf(fmaf(v.x, sc.x, sh.x), 0.f);
    v.y = fmaxf(fmaf(v.y, sc.y, sh.y), 0.f);
    v.z = fmaxf(fmaf(v.z, sc.z, sh.z), 0.f);
    v.w = fmaxf(fmaf(v.w, sc.w, sh.w), 0.f);
    float* dst = d_gsum + (size_t)b * H + lane * 4;
    asm volatile("red.global.add.v4.f32 [%0], {%1,%2,%3,%4};"
                 :: "l"(dst), "f"(v.x), "f"(v.y), "f"(v.z), "f"(v.w) : "memory");
    int* mdst = d_gmax + (size_t)b * H + lane * 4;
    atomicMax(mdst + 0, __float_as_int(v.x));  // post-ReLU >= 0: int order == float order
    atomicMax(mdst + 1, __float_as_int(v.y));
    atomicMax(mdst + 2, __float_as_int(v.z));
    atomicMax(mdst + 3, __float_as_int(v.w));
    if (lane == 0) atomicAdd(&d_gcnt[b], 1.0f);
}

// ---------------- MLP head: one block per graph ----------------
__global__ void __launch_bounds__(128)
mlp_kernel(const float* __restrict__ w1, const float* __restrict__ b1,
           const float* __restrict__ w2, const float* __restrict__ b2,
           const float* __restrict__ w3, const float* __restrict__ b3,
           float* __restrict__ out) {
    int g = blockIdx.x, t = threadIdx.x;
    __shared__ float gs[2 * H], h1s[H], h2s[64];
    float inv = 1.0f / fmaxf(d_gcnt[g], 1.0f);
    gs[t]     = d_gsum[(size_t)g * H + t] * inv;
    gs[H + t] = __int_as_float(d_gmax[(size_t)g * H + t]);
    __syncthreads();
    float a = b1[t];
#pragma unroll 8
    for (int k = 0; k < 2 * H; k++) a = fmaf(gs[k], w1[k * H + t], a);
    h1s[t] = fmaxf(a, 0.0f);
    __syncthreads();
    if (t < 64) {
        float a2 = b2[t];
#pragma unroll 8
        for (int k = 0; k < H; k++) a2 = fmaf(h1s[k], w2[k * 64 + t], a2);
        h2s[t] = fmaxf(a2, 0.0f);
    }
    __syncthreads();
    if (t < 32) {
        float s = h2s[t] * w3[t] + h2s[t + 32] * w3[t + 32];
        for (int o = 16; o; o >>= 1) s += __shfl_down_sync(0xffffffffu, s, o);
        if (t == 0) out[g] = s + b3[0];
    }
}

// ---------------- launch ----------------
extern "C" void kernel_launch(void* const* d_in, const int* in_sizes, int n_in,
                              void* d_out, int out_size) {
    const float* x      = (const float*)d_in[0];
    const int*   ei     = (const int*)  d_in[1];
    const int*   batch  = (const int*)  d_in[2];
    const float* emb_W  = (const float*)d_in[3];
    const float* emb_b  = (const float*)d_in[4];
    const float* conv_W = (const float*)d_in[5];
    const float* conv_b = (const float*)d_in[6];
    const float* bn_g   = (const float*)d_in[7];
    const float* bn_b   = (const float*)d_in[8];
    const float* w1     = (const float*)d_in[9];
    const float* b1     = (const float*)d_in[10];
    const float* w2     = (const float*)d_in[11];
    const float* b2     = (const float*)d_in[12];
    const float* w3     = (const float*)d_in[13];
    const float* b3     = (const float*)d_in[14];
    float* out = (float*)d_out;

    int N = in_sizes[0] / FIN;
    int E = in_sizes[1] / 2;
    int G = out_size;
    int n4 = N * 32;
    int nb = (N + 511) / 512;   // scan blocks (<= 512 required)

    float *ph = nullptr, *phn = nullptr;
    cudaGetSymbolAddress((void**)&ph, d_h);
    cudaGetSymbolAddress((void**)&phn, d_hn);

    int grid = (N + 63) / 64;

    // order chosen so the emb GEMM is the 4th launch (ncu captures launch #4)
    presplit_kernel<<<(4 * H * H) / 256, 256>>>(emb_W, conv_W);           // 1
    deg_init_kernel<<<(N + 255) / 256, 256>>>(N);                         // 2
    deg_edge_kernel<<<(E + 255) / 256, 256>>>(ei, E);                     // 3
    mma_gemm_kernel<<<grid, 256>>>(x, 0, emb_b, ph, N, FIN, 0, 0);        // 4 (profiled)
    deg_fin_kernel<<<(N + 255) / 256, 256>>>(N);                          // 5

    // CSR build
    scan1_kernel<<<nb, 512>>>(N);
    scan2_kernel<<<1, 512>>>(nb);
    scan3_kernel<<<(N + 255) / 256, 256>>>(N);
    place_kernel<<<(E + 255) / 256, 256>>>(ei, E);

    // GCN layers
    for (int l = 0; l < 3; l++) {
        const float* Ain = (l == 0) ? ph : phn;
        mma_gemm_kernel<<<grid, 256>>>(
            Ain, l + 1, conv_b + (size_t)l * H, nullptr, N, H, 1, (l == 0) ? 0 : 1);
        zero_stats_kernel<<<1, 256>>>();
        gather_kernel<<<(N + 7) / 8, 256>>>(N);
        bn_finalize_kernel<<<1, H>>>(bn_g + l * H, bn_b + l * H, 1.0f / (float)N);
    }

    // pooling (BN+ReLU of last layer fused) + head
    pool_init_kernel<<<(G * H + 255) / 256, 256>>>(G);
    pool_kernel<<<(n4 + 255) / 256, 256>>>(batch, N);
    mlp_kernel<<<G, H>>>(w1, b1, w2, b2, w3, b3, out);
}

// round 17
// speedup vs baseline: 1.6505x; 1.6505x over previous
#include <cuda_runtime.h>
#include <cuda_bf16.h>
#include <cstdint>

#define NMAX 100000
#define EMAX 600000
#define GMAX 4096
#define H 128
#define FIN 74

// ---------------- scratch (device globals; no allocations allowed) ----------------
__device__ __align__(16) float d_h [(size_t)NMAX * H];   // emb output
__device__ __align__(16) float d_hw[(size_t)NMAX * H];   // h @ W
__device__ __align__(16) float d_hn[(size_t)NMAX * H];   // aggregated messages (pre-BN)
__device__ __align__(16) float d_dinv[NMAX];             // deg -> rsqrt(deg)
__device__ __align__(16) float d_bnstats[2 * H];         // sum, sumsq
__device__ __align__(16) float d_scale[2 * H];           // scale, shift
__device__ __align__(16) float d_gsum[(size_t)GMAX * H];
__device__ __align__(16) int   d_gmax[(size_t)GMAX * H];
__device__ __align__(16) float d_gcnt[GMAX];
// CSR (dst-sorted edges)
__device__ int d_cnt[NMAX];
__device__ int d_start[NMAX];
__device__ int d_fill[NMAX];
__device__ int d_esrc[EMAX];
__device__ int d_bsum[256];
__device__ int d_boff[256];
// B in mma-fragment order: [mat][ks][n8][lane] = {bh0, bh1, bl0, bl1}
// mat 0 = emb (k >= 74 zero), 1..3 = conv layers.  4*8*16*32 uint4 = 256 KB.
__device__ __align__(16) uint4 d_WB[4 * 8 * 16 * 32];

// ---------------- degree + histogram ----------------
__global__ void deg_init_kernel(int N) {
    int i = blockIdx.x * blockDim.x + threadIdx.x;
    if (i < N) { d_dinv[i] = 1.0f; d_cnt[i] = 0; }
}
__global__ void deg_edge_kernel(const int* __restrict__ ei, int E) {
    int i = blockIdx.x * blockDim.x + threadIdx.x;
    if (i < E) {
        int d = ei[E + i];
        atomicAdd(&d_dinv[d], 1.0f);
        atomicAdd(&d_cnt[d], 1);
    }
}
__global__ void deg_fin_kernel(int N) {
    int i = blockIdx.x * blockDim.x + threadIdx.x;
    if (i < N) d_dinv[i] = rsqrtf(d_dinv[i]);
}
__global__ void zero_stats_kernel() {
    if (threadIdx.x < 2 * H) d_bnstats[threadIdx.x] = 0.0f;
}

// ---------------- 2-level exclusive scan of d_cnt -> d_start ----------------
__global__ void scan1_kernel(int N) {
    __shared__ int sh[512];
    int t = threadIdx.x;
    int i = blockIdx.x * 512 + t;
    int v = (i < N) ? d_cnt[i] : 0;
    sh[t] = v;
    __syncthreads();
    for (int off = 1; off < 512; off <<= 1) {
        int add = (t >= off) ? sh[t - off] : 0;
        __syncthreads();
        sh[t] += add;
        __syncthreads();
    }
    if (i < N) d_start[i] = sh[t] - v;
    if (t == 511) d_bsum[blockIdx.x] = sh[511];
}
__global__ void scan2_kernel(int nb) {
    __shared__ int sh[512];
    int t = threadIdx.x;
    int v = (t < nb) ? d_bsum[t] : 0;
    sh[t] = v;
    __syncthreads();
    for (int off = 1; off < 512; off <<= 1) {
        int add = (t >= off) ? sh[t - off] : 0;
        __syncthreads();
        sh[t] += add;
        __syncthreads();
    }
    if (t < nb) d_boff[t] = sh[t] - v;
}
__global__ void scan3_kernel(int N) {
    int i = blockIdx.x * blockDim.x + threadIdx.x;
    if (i < N) {
        int s = d_start[i] + d_boff[i >> 9];
        d_start[i] = s;
        d_fill[i] = s;
    }
}
__global__ void place_kernel(const int* __restrict__ ei, int E) {
    int i = blockIdx.x * blockDim.x + threadIdx.x;
    if (i < E) {
        int s = ei[i], d = ei[E + i];
        int pos = atomicAdd(&d_fill[d], 1);
        d_esrc[pos] = s;
    }
}

// ---------------- pre-split weights into fragment-major bf16 hi/lo ----------------
// For (mat, ks, n8, lane): n = n8*8 + (lane>>2), tg = lane&3, base k = ks*16 + 2*tg.
// uint4 = { hi(k,k+1), hi(k+8,k+9), lo(k,k+1), lo(k+8,k+9) }  (bf16x2 packs)
__global__ void presplit_kernel(const float* __restrict__ embW,
                                const float* __restrict__ convW) {
    int idx = blockIdx.x * 256 + threadIdx.x;   // < 16384
    int lane = idx & 31, n8 = (idx >> 5) & 15, ks = (idx >> 9) & 7, m = idx >> 12;
    int n = n8 * 8 + (lane >> 2);
    int k0 = ks * 16 + 2 * (lane & 3);
    float v[4];
#pragma unroll
    for (int q = 0; q < 4; q++) {
        int k = k0 + (q & 1) + (q >> 1) * 8;
        if (m == 0) v[q] = (k < FIN) ? embW[k * H + n] : 0.0f;
        else        v[q] = convW[(size_t)(m - 1) * H * H + k * H + n];
    }
    __nv_bfloat162 h0 = __floats2bfloat162_rn(v[0], v[1]);
    __nv_bfloat162 h1 = __floats2bfloat162_rn(v[2], v[3]);
    __nv_bfloat162 l0 = __floats2bfloat162_rn(v[0] - __bfloat162float(h0.x),
                                              v[1] - __bfloat162float(h0.y));
    __nv_bfloat162 l1 = __floats2bfloat162_rn(v[2] - __bfloat162float(h1.x),
                                              v[3] - __bfloat162float(h1.y));
    uint4 o;
    o.x = *reinterpret_cast<uint32_t*>(&h0);
    o.y = *reinterpret_cast<uint32_t*>(&h1);
    o.z = *reinterpret_cast<uint32_t*>(&l0);
    o.w = *reinterpret_cast<uint32_t*>(&l1);
    d_WB[idx] = o;
}

// ---------------- tensor-core GEMM (bf16 split, fp32 accumulate) ----------------
__device__ __forceinline__ void mma_bf16(float* c, const uint32_t* a, const uint32_t* b) {
    asm volatile("mma.sync.aligned.m16n8k16.row.col.f32.bf16.bf16.f32 "
                 "{%0,%1,%2,%3}, {%4,%5,%6,%7}, {%8,%9}, {%0,%1,%2,%3};"
                 : "+f"(c[0]), "+f"(c[1]), "+f"(c[2]), "+f"(c[3])
                 : "r"(a[0]), "r"(a[1]), "r"(a[2]), "r"(a[3]), "r"(b[0]), "r"(b[1]));
}

#define LDK 132   // bf16 per smem row (128 + 4 pad)

// Fully-unrolled mainloop: per ks, A = 16 LDS.32 (hi+lo frag), B = 4 LDG.128.
template<int NKS>
__device__ __forceinline__ void gemm_mainloop(
    const __nv_bfloat16* AH, const __nv_bfloat16* AL, const uint4* WBm,
    int wm, int wn, int g, int tg, int lane, float (&acc)[2][4][4]) {
#pragma unroll
    for (int ks = 0; ks < NKS; ks++) {
        int k0 = ks * 16;
        uint32_t ah[2][4], alr[2][4];
        uint4 bf[4];
#pragma unroll
        for (int j = 0; j < 4; j++)
            bf[j] = WBm[(size_t)((ks * 16 + wn * 4 + j) * 32 + lane)];
#pragma unroll
        for (int i2 = 0; i2 < 2; i2++) {
            int r = wm * 32 + i2 * 16 + g;
            const uint32_t* ph  = (const uint32_t*)(AH + r * LDK + k0);
            const uint32_t* ph8 = (const uint32_t*)(AH + (r + 8) * LDK + k0);
            const uint32_t* pl  = (const uint32_t*)(AL + r * LDK + k0);
            const uint32_t* pl8 = (const uint32_t*)(AL + (r + 8) * LDK + k0);
            ah[i2][0] = ph[tg];     ah[i2][1] = ph8[tg];
            ah[i2][2] = ph[tg + 4]; ah[i2][3] = ph8[tg + 4];
            alr[i2][0] = pl[tg];     alr[i2][1] = pl8[tg];
            alr[i2][2] = pl[tg + 4]; alr[i2][3] = pl8[tg + 4];
        }
#pragma unroll
        for (int i2 = 0; i2 < 2; i2++)
#pragma unroll
            for (int j = 0; j < 4; j++) {
                uint32_t bh[2]  = { bf[j].x, bf[j].y };
                uint32_t blr[2] = { bf[j].z, bf[j].w };
                mma_bf16(acc[i2][j], ah[i2], bh);
                mma_bf16(acc[i2][j], alr[i2], bh);
                mma_bf16(acc[i2][j], ah[i2], blr);
            }
    }
}

// C[N][128] = A[N][K] @ W_mat[K][128].  Block: 64 rows, 256 thr (8 warps 2x4,
// each warp a 32x32 tile).  A staged in smem as bf16 hi/lo; B fragment-major global.
// mode 0 (emb): Cout = relu(A@B + bias)
// mode 1 (conv): d_hw = A@B ; d_hn = (A@B)*dinv[r]^2 + bias ; bna: BN+ReLU on A load.
__global__ void __launch_bounds__(256)
mma_gemm_kernel(const float* __restrict__ A, int mat,
                const float* __restrict__ bias, float* __restrict__ Cout,
                int N, int K, int mode, int bna) {
    __shared__ __align__(16) __nv_bfloat16 AH[64 * LDK];
    __shared__ __align__(16) __nv_bfloat16 AL[64 * LDK];

    int tid = threadIdx.x;
    int rowBase = blockIdx.x * 64;

    // ---- stage A (64 x 128), split hi/lo ----
    if (K == 128) {
        const float4* A4 = (const float4*)A;
        const float4* sc4 = (const float4*)d_scale;
        for (int i = tid; i < 64 * 32; i += 256) {
            int r = i >> 5, k4 = i & 31;
            int gr = rowBase + r;
            float4 v = make_float4(0.f, 0.f, 0.f, 0.f);
            if (gr < N) v = A4[(size_t)gr * 32 + k4];
            if (bna) {
                float4 s = sc4[k4], b = sc4[32 + k4];
                v.x = fmaxf(fmaf(v.x, s.x, b.x), 0.f);
                v.y = fmaxf(fmaf(v.y, s.y, b.y), 0.f);
                v.z = fmaxf(fmaf(v.z, s.z, b.z), 0.f);
                v.w = fmaxf(fmaf(v.w, s.w, b.w), 0.f);
            }
            __nv_bfloat162 h01 = __floats2bfloat162_rn(v.x, v.y);
            __nv_bfloat162 h23 = __floats2bfloat162_rn(v.z, v.w);
            __nv_bfloat162 l01 = __floats2bfloat162_rn(
                v.x - __bfloat162float(h01.x), v.y - __bfloat162float(h01.y));
            __nv_bfloat162 l23 = __floats2bfloat162_rn(
                v.z - __bfloat162float(h23.x), v.w - __bfloat162float(h23.y));
            uint2 uh, ul;
            uh.x = *reinterpret_cast<uint32_t*>(&h01);
            uh.y = *reinterpret_cast<uint32_t*>(&h23);
            ul.x = *reinterpret_cast<uint32_t*>(&l01);
            ul.y = *reinterpret_cast<uint32_t*>(&l23);
            *(uint2*)&AH[r * LDK + k4 * 4] = uh;
            *(uint2*)&AL[r * LDK + k4 * 4] = ul;
        }
    } else {
        for (int i = tid; i < 64 * 128; i += 256) {
            int r = i >> 7, k = i & 127;
            int gr = rowBase + r;
            float v = 0.0f;
            if (gr < N && k < K) v = A[(size_t)gr * K + k];
            __nv_bfloat16 hv = __float2bfloat16(v);
            AH[r * LDK + k] = hv;
            AL[r * LDK + k] = __float2bfloat16(v - __bfloat162float(hv));
        }
    }
    __syncthreads();

    int lane = tid & 31, wid = tid >> 5;
    int wm = wid & 1;        // m offset 32*wm
    int wn = wid >> 1;       // n offset 32*wn
    int g = lane >> 2, tg = lane & 3;

    const uint4* WBm = d_WB + (size_t)mat * 8 * 16 * 32;

    float acc[2][4][4];
#pragma unroll
    for (int i2 = 0; i2 < 2; i2++)
#pragma unroll
        for (int j = 0; j < 4; j++)
#pragma unroll
            for (int e = 0; e < 4; e++) acc[i2][j][e] = 0.0f;

    if (K == 128) gemm_mainloop<8>(AH, AL, WBm, wm, wn, g, tg, lane, acc);
    else          gemm_mainloop<5>(AH, AL, WBm, wm, wn, g, tg, lane, acc);

    // ---- epilogue ----
#pragma unroll
    for (int i2 = 0; i2 < 2; i2++) {
#pragma unroll
        for (int half = 0; half < 2; half++) {
            int r = rowBase + wm * 32 + i2 * 16 + g + half * 8;
            if (r >= N) continue;
            if (mode == 0) {
#pragma unroll
                for (int j = 0; j < 4; j++) {
                    int c = wn * 32 + j * 8 + tg * 2;
                    float2 o;
                    o.x = fmaxf(acc[i2][j][half * 2 + 0] + bias[c], 0.0f);
                    o.y = fmaxf(acc[i2][j][half * 2 + 1] + bias[c + 1], 0.0f);
                    *(float2*)&Cout[(size_t)r * H + c] = o;
                }
            } else {
                float dv = d_dinv[r];
                float w = dv * dv;
#pragma unroll
                for (int j = 0; j < 4; j++) {
                    int c = wn * 32 + j * 8 + tg * 2;
                    float v0 = acc[i2][j][half * 2 + 0];
                    float v1 = acc[i2][j][half * 2 + 1];
                    *(float2*)&d_hw[(size_t)r * H + c] = make_float2(v0, v1);
                    float2 o;
                    o.x = fmaf(v0, w, bias[c]);
                    o.y = fmaf(v1, w, bias[c + 1]);
                    *(float2*)&d_hn[(size_t)r * H + c] = o;
                }
            }
        }
    }
}

// ---------------- CSR gather (warp per node, no atomics) ----------------
__global__ void gather_kernel(int N) {
    unsigned i = blockIdx.x * blockDim.x + threadIdx.x;
    unsigned n = i >> 5;
    if (n >= (unsigned)N) return;
    int lane = i & 31;
    float4* hn4 = (float4*)d_hn;
    const float4* hw4 = (const float4*)d_hw;
    float4 acc = hn4[(size_t)n * 32 + lane];
    int st = d_start[n];
    int en = st + d_cnt[n];
    float dvd = d_dinv[n];
    for (int e = st; e < en; e++) {
        int s = d_esrc[e];
        float nrm = d_dinv[s] * dvd;
        float4 v = hw4[(size_t)s * 32 + lane];
        acc.x = fmaf(v.x, nrm, acc.x);
        acc.y = fmaf(v.y, nrm, acc.y);
        acc.z = fmaf(v.z, nrm, acc.z);
        acc.w = fmaf(v.w, nrm, acc.w);
    }
    hn4[(size_t)n * 32 + lane] = acc;
}

// ---------------- BatchNorm stats (sum, sumsq per channel) ----------------
__global__ void bn_stats_kernel(int N) {
    int c = threadIdx.x & (H - 1);
    int half = threadIdx.x >> 7;
    int base = blockIdx.x * 512;
    int end = min(base + 512, N);
    float s = 0.0f, q = 0.0f;
    for (int r = base + half; r < end; r += 2) {
        float v = d_hn[(size_t)r * H + c];
        s += v; q += v * v;
    }
    __shared__ float sh[512];
    sh[threadIdx.x] = s;
    sh[256 + threadIdx.x] = q;
    __syncthreads();
    if (threadIdx.x < H) {
        atomicAdd(&d_bnstats[c], sh[c] + sh[H + c]);
        atomicAdd(&d_bnstats[H + c], sh[256 + c] + sh[256 + H + c]);
    }
}

__global__ void bn_finalize_kernel(const float* __restrict__ gamma,
                                   const float* __restrict__ beta, float invN) {
    int c = threadIdx.x;
    float mean = d_bnstats[c] * invN;
    float var = d_bnstats[H + c] * invN - mean * mean;
    float sc = gamma[c] * rsqrtf(var + 1e-5f);
    d_scale[c] = sc;
    d_scale[H + c] = beta[c] - mean * sc;
}

// ---------------- pooling (mean + max per graph), fused BN+ReLU of last layer ----------------
__global__ void pool_init_kernel(int G) {
    int i = blockIdx.x * blockDim.x + threadIdx.x;
    if (i < G * H) { d_gsum[i] = 0.0f; d_gmax[i] = 0; }
    if (i < G) d_gcnt[i] = 0.0f;
}

__global__ void pool_kernel(const int* __restrict__ batch, int N) {
    unsigned i = blockIdx.x * blockDim.x + threadIdx.x;
    unsigned n = i >> 5;
    if (n >= (unsigned)N) return;
    int lane = i & 31;
    int b = batch[n];
    float4 v  = ((const float4*)d_hn)[(size_t)n * 32 + lane];
    float4 sc = ((const float4*)d_scale)[lane];
    float4 sh = ((const float4*)d_scale)[32 + lane];
    v.x = fmaxf(fmaf(v.x, sc.x, sh.x), 0.f);
    v.y = fmaxf(fmaf(v.y, sc.y, sh.y), 0.f);
    v.z = fmaxf(fmaf(v.z, sc.z, sh.z), 0.f);
    v.w = fmaxf(fmaf(v.w, sc.w, sh.w), 0.f);
    float* dst = d_gsum + (size_t)b * H + lane * 4;
    asm volatile("red.global.add.v4.f32 [%0], {%1,%2,%3,%4};"
                 :: "l"(dst), "f"(v.x), "f"(v.y), "f"(v.z), "f"(v.w) : "memory");
    int* mdst = d_gmax + (size_t)b * H + lane * 4;
    atomicMax(mdst + 0, __float_as_int(v.x));
    atomicMax(mdst + 1, __float_as_int(v.y));
    atomicMax(mdst + 2, __float_as_int(v.z));
    atomicMax(mdst + 3, __float_as_int(v.w));
    if (lane == 0) atomicAdd(&d_gcnt[b], 1.0f);
}

// ---------------- MLP head: one block per graph ----------------
__global__ void __launch_bounds__(128)
mlp_kernel(const float* __restrict__ w1, const float* __restrict__ b1,
           const float* __restrict__ w2, const float* __restrict__ b2,
           const float* __restrict__ w3, const float* __restrict__ b3,
           float* __restrict__ out) {
    int g = blockIdx.x, t = threadIdx.x;
    __shared__ float gs[2 * H], h1s[H], h2s[64];
    float inv = 1.0f / fmaxf(d_gcnt[g], 1.0f);
    gs[t]     = d_gsum[(size_t)g * H + t] * inv;
    gs[H + t] = __int_as_float(d_gmax[(size_t)g * H + t]);
    __syncthreads();
    float a = b1[t];
#pragma unroll 8
    for (int k = 0; k < 2 * H; k++) a = fmaf(gs[k], w1[k * H + t], a);
    h1s[t] = fmaxf(a, 0.0f);
    __syncthreads();
    if (t < 64) {
        float a2 = b2[t];
#pragma unroll 8
        for (int k = 0; k < H; k++) a2 = fmaf(h1s[k], w2[k * 64 + t], a2);
        h2s[t] = fmaxf(a2, 0.0f);
    }
    __syncthreads();
    if (t < 32) {
        float s = h2s[t] * w3[t] + h2s[t + 32] * w3[t + 32];
        for (int o = 16; o; o >>= 1) s += __shfl_down_sync(0xffffffffu, s, o);
        if (t == 0) out[g] = s + b3[0];
    }
}

// ---------------- launch ----------------
extern "C" void kernel_launch(void* const* d_in, const int* in_sizes, int n_in,
                              void* d_out, int out_size) {
    const float* x      = (const float*)d_in[0];
    const int*   ei     = (const int*)  d_in[1];
    const int*   batch  = (const int*)  d_in[2];
    const float* emb_W  = (const float*)d_in[3];
    const float* emb_b  = (const float*)d_in[4];
    const float* conv_W = (const float*)d_in[5];
    const float* conv_b = (const float*)d_in[6];
    const float* bn_g   = (const float*)d_in[7];
    const float* bn_b   = (const float*)d_in[8];
    const float* w1     = (const float*)d_in[9];
    const float* b1     = (const float*)d_in[10];
    const float* w2     = (const float*)d_in[11];
    const float* b2     = (const float*)d_in[12];
    const float* w3     = (const float*)d_in[13];
    const float* b3     = (const float*)d_in[14];
    float* out = (float*)d_out;

    int N = in_sizes[0] / FIN;
    int E = in_sizes[1] / 2;
    int G = out_size;
    int n4 = N * 32;
    int nb = (N + 511) / 512;

    float *ph = nullptr, *phn = nullptr;
    cudaGetSymbolAddress((void**)&ph, d_h);
    cudaGetSymbolAddress((void**)&phn, d_hn);

    int grid = (N + 63) / 64;

    // order: emb GEMM is the 4th launch (ncu captures launch #4)
    presplit_kernel<<<64, 256>>>(emb_W, conv_W);                          // 1
    deg_init_kernel<<<(N + 255) / 256, 256>>>(N);                         // 2
    deg_edge_kernel<<<(E + 255) / 256, 256>>>(ei, E);                     // 3
    mma_gemm_kernel<<<grid, 256>>>(x, 0, emb_b, ph, N, FIN, 0, 0);        // 4 (profiled)
    deg_fin_kernel<<<(N + 255) / 256, 256>>>(N);                          // 5

    // CSR build
    scan1_kernel<<<nb, 512>>>(N);
    scan2_kernel<<<1, 512>>>(nb);
    scan3_kernel<<<(N + 255) / 256, 256>>>(N);
    place_kernel<<<(E + 255) / 256, 256>>>(ei, E);

    // GCN layers
    for (int l = 0; l < 3; l++) {
        const float* Ain = (l == 0) ? ph : phn;
        mma_gemm_kernel<<<grid, 256>>>(
            Ain, l + 1, conv_b + (size_t)l * H, nullptr, N, H, 1, (l == 0) ? 0 : 1);
        gather_kernel<<<(N * 32 + 255) / 256, 256>>>(N);
        zero_stats_kernel<<<1, 256>>>();
        bn_stats_kernel<<<(N + 511) / 512, 256>>>(N);
        bn_finalize_kernel<<<1, H>>>(bn_g + l * H, bn_b + l * H, 1.0f / (float)N);
    }

    // pooling (BN+ReLU of last layer fused) + head
    pool_init_kernel<<<(G * H + 255) / 256, 256>>>(G);
    pool_kernel<<<(n4 + 255) / 256, 256>>>(batch, N);
    mlp_kernel<<<G, H>>>(w1, b1, w2, b2, w3, b3, out);
}